// round 16
// baseline (speedup 1.0000x reference)
#include <cuda_runtime.h>
#include <cuda_fp16.h>
#include <math.h>

#define NN 4096
#define CC 512
#define HH 8
#define DD 64
#define EE 131072
#define QL 2048

typedef __half h16;
typedef unsigned int u32;

// ---------------- scratch ----------------
__device__ h16   g_mean16[NN * CC];
__device__ int   g_icnt[NN];
__device__ int   g_offs[NN];
__device__ int   g_rank[EE];
__device__ int   g_ssorted[EE];
__device__ h16   g_x16[NN * CC];
__device__ h16   g_qw16[QL * CC];
__device__ float g_biasq[QL];
__device__ h16   g_qkvl16[NN * QL];
__device__ h16   g_ctx16[NN * CC];
__device__ float g_T[NN * CC];
__device__ float g_h1[NN * CC];
__device__ float g_hid[NN * CC];
__device__ h16   g_hid16[NN * CC];
__device__ h16   g_f116[NN * 2 * CC];
__device__ float g_h2[NN * CC];
__device__ h16   g_aowT16[CC * CC];
__device__ h16   g_ow16[CC * CC];
__device__ h16   g_cw16[CC * CC];
__device__ float g_biasc[CC];
__device__ h16   g_w116[2 * CC * CC];
__device__ h16   g_w216[2 * CC * CC];

#define EPI_NONE          0
#define EPI_BIAS          1
#define EPI_BIAS_GELU     2
#define EPI_BIAS_RES      4
#define EPI_HALF_BIAS_RES 6
#define EPI_HALF_RES      7

__device__ __forceinline__ float gelu_exact(float v) {
    return 0.5f * v * (1.0f + erff(v * 0.70710678118654752f));
}
__device__ __forceinline__ u32 smem_cast(const void* p) {
    u32 a;
    asm("{ .reg .u64 t; cvta.to.shared.u64 t, %1; cvt.u32.u64 %0, t; }" : "=r"(a) : "l"(p));
    return a;
}
__device__ __forceinline__ void cpasync16(u32 s, const void* g) {
    asm volatile("cp.async.cg.shared.global [%0], [%1], 16;\n" :: "r"(s), "l"(g));
}
__device__ __forceinline__ void cp_commit() { asm volatile("cp.async.commit_group;\n" ::); }
__device__ __forceinline__ void cp_wait0() { asm volatile("cp.async.wait_group 0;\n" ::); }
__device__ __forceinline__ void cp_wait2() { asm volatile("cp.async.wait_group 2;\n" ::); }

__device__ __forceinline__ void ldm4(u32 addr, u32& r0, u32& r1, u32& r2, u32& r3) {
    asm volatile("ldmatrix.sync.aligned.m8n8.x4.shared.b16 {%0,%1,%2,%3}, [%4];"
                 : "=r"(r0), "=r"(r1), "=r"(r2), "=r"(r3) : "r"(addr));
}
__device__ __forceinline__ void ldm4t(u32 addr, u32& r0, u32& r1, u32& r2, u32& r3) {
    asm volatile("ldmatrix.sync.aligned.m8n8.x4.trans.shared.b16 {%0,%1,%2,%3}, [%4];"
                 : "=r"(r0), "=r"(r1), "=r"(r2), "=r"(r3) : "r"(addr));
}
__device__ __forceinline__ void mmah(float* c, const u32* a, const u32* b) {
    asm volatile("mma.sync.aligned.m16n8k16.row.col.f32.f16.f16.f32 "
                 "{%0,%1,%2,%3}, {%4,%5,%6,%7}, {%8,%9}, {%0,%1,%2,%3};"
                 : "+f"(c[0]), "+f"(c[1]), "+f"(c[2]), "+f"(c[3])
                 : "r"(a[0]), "r"(a[1]), "r"(a[2]), "r"(a[3]), "r"(b[0]), "r"(b[1]));
}
__device__ __forceinline__ int swz(int m, int kc) {
    return (m * 4 + (kc ^ ((m >> 1) & 3))) * 16;
}
__device__ __forceinline__ int swz8(int m, int kc) {
    return (m * 8 + (kc ^ (m & 7))) * 16;
}
__device__ __forceinline__ float qsum(float v) {
    v += __shfl_xor_sync(0xffffffff, v, 1);
    v += __shfl_xor_sync(0xffffffff, v, 2);
    return v;
}
__device__ __forceinline__ u32 packh2(float a, float b) {
    __half2 t = __floats2half2_rn(a, b);
    return *(u32*)&t;
}
__device__ __forceinline__ u32 h2ex2(u32 x) {
    u32 r;
    asm("ex2.approx.f16x2 %0, %1;" : "=r"(r) : "r"(x));
    return r;
}
__device__ __forceinline__ __half2 ash2(u32 x) { return *(__half2*)&x; }

// ---------------- fp16 HMMA GEMM, tile 128x128x32, 3-stage pipeline ----------------
template<int EPI, int WF32, int WHALF>
__global__ __launch_bounds__(256, 2)
void gemm_h(const h16* __restrict__ A, int lda,
            const h16* __restrict__ B, int ldb,
            float* __restrict__ C, h16* __restrict__ Ch, int ldc,
            int K, const float* __restrict__ bias, const float* __restrict__ res)
{
    __shared__ __align__(16) char smem[49152];
    const u32 sb = smem_cast(smem);
    const int tid = threadIdx.x;
    const int m0 = blockIdx.y * 128, n0 = blockIdx.x * 128;
    const int lm = tid >> 2, lkc = tid & 3;
    const h16* ag0 = A + (size_t)(m0 + lm) * lda + lkc * 8;
    const h16* ag1 = A + (size_t)(m0 + lm + 64) * lda + lkc * 8;
    const h16* bg0 = B + (size_t)(n0 + lm) * ldb + lkc * 8;
    const h16* bg1 = B + (size_t)(n0 + lm + 64) * ldb + lkc * 8;
    const int da0 = swz(lm, lkc), da1 = swz(lm + 64, lkc);
    const int lane = tid & 31, warp = tid >> 5;
    const int wm = warp & 3, wn = warp >> 2;
    const int lrow = lane & 15, lhalf = lane >> 4;
    const int am0 = wm * 32 + lrow, bn0 = wn * 64 + lrow;
    float acc[2][8][4] = {};
    const int NK = K >> 5;   // always >= 16 here

#define LOAD_CHUNK(k0, s) { \
        u32 st = sb + (s) * 16384; \
        cpasync16(st + da0,        ag0 + (k0)); \
        cpasync16(st + da1,        ag1 + (k0)); \
        cpasync16(st + 8192 + da0, bg0 + (k0)); \
        cpasync16(st + 8192 + da1, bg1 + (k0)); \
        cp_commit(); }

    LOAD_CHUNK(0, 0);
    LOAD_CHUNK(32, 1);
    LOAD_CHUNK(64, 2);
    for (int i = 0; i < NK; i++) {
        cp_wait2();
        __syncthreads();
        const u32 st = sb + (i % 3) * 16384;
        #pragma unroll
        for (int ks = 0; ks < 2; ks++) {
            const int kc = ks * 2 + lhalf;
            u32 a[2][4], b[8][2];
            #pragma unroll
            for (int mi = 0; mi < 2; mi++)
                ldm4(st + swz(am0 + mi * 16, kc), a[mi][0], a[mi][1], a[mi][2], a[mi][3]);
            #pragma unroll
            for (int p = 0; p < 4; p++) {
                u32 q0, q1, q2, q3;
                ldm4(st + 8192 + swz(bn0 + p * 16, kc), q0, q1, q2, q3);
                b[2 * p][0] = q0; b[2 * p][1] = q2;
                b[2 * p + 1][0] = q1; b[2 * p + 1][1] = q3;
            }
            #pragma unroll
            for (int mi = 0; mi < 2; mi++)
                #pragma unroll
                for (int ni = 0; ni < 8; ni++)
                    mmah(acc[mi][ni], a[mi], b[ni]);
        }
        __syncthreads();
        if (i + 3 < NK) LOAD_CHUNK((i + 3) * 32, (i + 3) % 3);
    }
#undef LOAD_CHUNK
    #pragma unroll
    for (int mi = 0; mi < 2; mi++)
        #pragma unroll
        for (int ni = 0; ni < 8; ni++) {
            int row = m0 + wm * 32 + mi * 16 + (lane >> 2);
            int col = n0 + wn * 64 + ni * 8 + (lane & 3) * 2;
            float2 bv = make_float2(0.f, 0.f);
            if (EPI == EPI_BIAS || EPI == EPI_BIAS_GELU ||
                EPI == EPI_BIAS_RES || EPI == EPI_HALF_BIAS_RES)
                bv = *(const float2*)&bias[col];
            #pragma unroll
            for (int rr = 0; rr < 2; rr++) {
                int r = row + rr * 8;
                float v0 = acc[mi][ni][rr * 2 + 0];
                float v1 = acc[mi][ni][rr * 2 + 1];
                if (EPI == EPI_HALF_BIAS_RES || EPI == EPI_HALF_RES) {
                    v0 *= 0.5f; v1 *= 0.5f;
                }
                if (EPI == EPI_BIAS || EPI == EPI_BIAS_GELU ||
                    EPI == EPI_BIAS_RES || EPI == EPI_HALF_BIAS_RES) {
                    v0 += bv.x; v1 += bv.y;
                }
                if (EPI == EPI_BIAS_RES || EPI == EPI_HALF_BIAS_RES ||
                    EPI == EPI_HALF_RES) {
                    float2 rv = *(const float2*)&res[(size_t)r * ldc + col];
                    v0 += rv.x; v1 += rv.y;
                }
                if (EPI == EPI_BIAS_GELU) { v0 = gelu_exact(v0); v1 = gelu_exact(v1); }
                if (WF32)
                    *(float2*)&C[(size_t)r * ldc + col] = make_float2(v0, v1);
                if (WHALF)
                    *(u32*)&Ch[(size_t)r * ldc + col] = packh2(v0, v1);
            }
        }
}

// ---------------- flash attention (unchanged; at HMMA floor) ----------------
#define FSTAGE 16384

__global__ void __launch_bounds__(256, 2)
flash_kernel(const h16* __restrict__ qkv, h16* __restrict__ ctx)
{
    extern __shared__ __align__(16) char sm[];
    const u32 sb = smem_cast(sm);
    const int h = blockIdx.y;
    const int q0row = blockIdx.x * 128;
    const int tid = threadIdx.x, lane = tid & 31, warp = tid >> 5;
    const int lrow = lane & 15, lhalf = lane >> 4;
    const float LSC = 0.125f * 1.44269504088896340736f;

    #pragma unroll
    for (int i = 0; i < 4; i++) {
        int idx = tid + i * 256;
        int r = idx >> 3, kc = idx & 7;
        cpasync16(sb + swz8(r, kc),
                  qkv + (size_t)(q0row + r) * QL + h * 64 + kc * 8);
    }
    cp_commit();
    cp_wait0();
    __syncthreads();

    u32 qh[4][4];
    {
        int m = warp * 16 + lrow;
        #pragma unroll
        for (int ks = 0; ks < 4; ks++) {
            int kc = ks * 2 + lhalf;
            ldm4(sb + swz8(m, kc), qh[ks][0], qh[ks][1], qh[ks][2], qh[ks][3]);
        }
    }
    __syncthreads();

#define FLOAD(slot, itv) {                                                       \
        u32 st_ = sb + (slot) * FSTAGE;                                          \
        int kb_ = (itv) * 64;                                                    \
        _Pragma("unroll")                                                        \
        for (int i_ = 0; i_ < 2; i_++) {                                         \
            int idx_ = tid + i_ * 256;                                           \
            int r_ = idx_ >> 3, kc_ = idx_ & 7;                                  \
            cpasync16(st_ + swz8(r_, kc_),                                       \
                      qkv + (size_t)(kb_ + r_) * QL + 512 + h * 64 + kc_ * 8);   \
            cpasync16(st_ + 8192 + swz8(r_, kc_),                                \
                      qkv + (size_t)(kb_ + r_) * QL + 1024 + h * 64 + kc_ * 8);  \
        }                                                                        \
        cp_commit();                                                             \
    }

    float oacc[8][4] = {};
    float l0v = 0.f, l1v = 0.f;

    FLOAD(0, 0);
    FLOAD(1, 1);
    FLOAD(2, 2);

    for (int it = 0; it < 64; it++) {
        cp_wait2();
        __syncthreads();
        const u32 st = sb + (it % 3) * FSTAGE;

        float sacc[8][4] = {};
        #pragma unroll
        for (int ks = 0; ks < 4; ks++) {
            const int kc = ks * 2 + lhalf;
            u32 b[8][2];
            #pragma unroll
            for (int p = 0; p < 4; p++) {
                u32 q0, q1, q2, q3;
                ldm4(st + swz8(p * 16 + lrow, kc), q0, q1, q2, q3);
                b[2 * p][0] = q0; b[2 * p][1] = q2;
                b[2 * p + 1][0] = q1; b[2 * p + 1][1] = q3;
            }
            #pragma unroll
            for (int n = 0; n < 8; n++)
                mmah(sacc[n], qh[ks], b[n]);
        }

        u32 ph[4][4];
        #pragma unroll
        for (int k2 = 0; k2 < 4; k2++) {
            ph[k2][0] = h2ex2(packh2(sacc[2 * k2][0] * LSC,     sacc[2 * k2][1] * LSC));
            ph[k2][1] = h2ex2(packh2(sacc[2 * k2][2] * LSC,     sacc[2 * k2][3] * LSC));
            ph[k2][2] = h2ex2(packh2(sacc[2 * k2 + 1][0] * LSC, sacc[2 * k2 + 1][1] * LSC));
            ph[k2][3] = h2ex2(packh2(sacc[2 * k2 + 1][2] * LSC, sacc[2 * k2 + 1][3] * LSC));
        }

        {
            __half2 t0 = __hadd2(__hadd2(ash2(ph[0][0]), ash2(ph[0][2])),
                                 __hadd2(ash2(ph[1][0]), ash2(ph[1][2])));
            t0 = __hadd2(t0, __hadd2(__hadd2(ash2(ph[2][0]), ash2(ph[2][2])),
                                     __hadd2(ash2(ph[3][0]), ash2(ph[3][2]))));
            __half2 t1 = __hadd2(__hadd2(ash2(ph[0][1]), ash2(ph[0][3])),
                                 __hadd2(ash2(ph[1][1]), ash2(ph[1][3])));
            t1 = __hadd2(t1, __hadd2(__hadd2(ash2(ph[2][1]), ash2(ph[2][3])),
                                     __hadd2(ash2(ph[3][1]), ash2(ph[3][3]))));
            float2 f0 = __half22float2(t0), f1 = __half22float2(t1);
            l0v += f0.x + f0.y;
            l1v += f1.x + f1.y;
        }

        #pragma unroll
        for (int ks = 0; ks < 4; ks++) {
            u32 v[8][2];
            #pragma unroll
            for (int p = 0; p < 4; p++) {
                u32 q0, q1, q2, q3;
                ldm4t(st + 8192 + swz8(ks * 16 + lrow, p * 2 + lhalf), q0, q1, q2, q3);
                v[2 * p][0] = q0; v[2 * p][1] = q1;
                v[2 * p + 1][0] = q2; v[2 * p + 1][1] = q3;
            }
            #pragma unroll
            for (int n = 0; n < 8; n++)
                mmah(oacc[n], ph[ks], v[n]);
        }

        __syncthreads();
        if (it + 3 < 64) FLOAD(it % 3, it + 3);
    }
#undef FLOAD

    l0v = qsum(l0v);
    l1v = qsum(l1v);
    float inv0 = 1.f / l0v, inv1 = 1.f / l1v;
    int r0 = q0row + warp * 16 + (lane >> 2);
    int col0 = h * 64 + (lane & 3) * 2;
    #pragma unroll
    for (int n = 0; n < 8; n++) {
        size_t i0 = (size_t)r0 * CC + col0 + n * 8;
        size_t i1 = (size_t)(r0 + 8) * CC + col0 + n * 8;
        *(u32*)&ctx[i0] = packh2(oacc[n][0] * inv0, oacc[n][1] * inv0);
        *(u32*)&ctx[i1] = packh2(oacc[n][2] * inv1, oacc[n][3] * inv1);
    }
}

// ---------------- converts ----------------
// stream0: x only
__global__ void cvt_x(const float* __restrict__ x, h16* __restrict__ x16)
{
    int i = (blockIdx.x * 256 + threadIdx.x) * 2;
    float2 v = *(const float2*)&x[i];
    *(u32*)&x16[i] = packh2(v.x, v.y);
}

// s1: ipw | lw -> qw ; biasq pack
__global__ void cvt_qw(const float* __restrict__ ipw, const float* __restrict__ lw,
                       const float* __restrict__ ipb, const float* __restrict__ lb,
                       h16* qw16, float* biasq)
{
    int gid = blockIdx.x * 256 + threadIdx.x;
    if (gid < QL / 2) {
        int i2 = gid * 2;
        biasq[i2]     = (i2 < 1536)     ? ipb[i2]     : lb[i2 - 1536];
        biasq[i2 + 1] = (i2 + 1 < 1536) ? ipb[i2 + 1] : lb[i2 + 1 - 1536];
    }
    int i = gid * 2;
    const float* in; h16* o; int j;
    if (i < 786432) { in = ipw; o = qw16;          j = i; }
    else            { in = lw;  o = qw16 + 786432; j = i - 786432; }
    float2 v = *(const float2*)&in[j];
    *(u32*)&o[j] = packh2(v.x, v.y);
}

// s1: ow | w1 | w2
__global__ void cvt_rest(const float* __restrict__ ow, const float* __restrict__ w1,
                         const float* __restrict__ w2,
                         h16* ow16, h16* w116, h16* w216)
{
    int i = (blockIdx.x * 256 + threadIdx.x) * 2;
    const float* in; h16* o; int j;
    if      (i < 262144)  { in = ow; o = ow16;  j = i; }
    else if (i < 786432)  { in = w1; o = w116;  j = i - 262144; }
    else                  { in = w2; o = w216;  j = i - 786432; }
    float2 v = *(const float2*)&in[j];
    *(u32*)&o[j] = packh2(v.x, v.y);
}

__global__ void taow_kernel(const float* __restrict__ aow, h16* __restrict__ aowT)
{
    __shared__ float t[32][33];
    int c0 = blockIdx.x * 32, r0 = blockIdx.y * 32;
    int tx = threadIdx.x, ty = threadIdx.y;
    #pragma unroll
    for (int i = 0; i < 32; i += 8)
        t[ty + i][tx] = aow[(size_t)(r0 + ty + i) * CC + c0 + tx];
    __syncthreads();
    #pragma unroll
    for (int i = 0; i < 32; i += 8)
        aowT[(size_t)(c0 + ty + i) * CC + r0 + tx] = __float2half_rn(t[tx][ty + i]);
}

__global__ void biasc_kernel(const float* __restrict__ ow, const float* __restrict__ ba,
                             const float* __restrict__ bo, float* __restrict__ bc)
{
    __shared__ float r[128];
    int i = blockIdx.x, t = threadIdx.x;
    float s = 0.f;
    for (int j = t; j < CC; j += 128) s += ba[j] * ow[(size_t)i * CC + j];
    r[t] = s;
    __syncthreads();
    for (int st = 64; st > 0; st >>= 1) {
        if (t < st) r[t] += r[t + st];
        __syncthreads();
    }
    if (t == 0) bc[i] = 0.5f * r[0] + bo[i];
}

// ---------------- layer norm ----------------
template<int WHALF>
__global__ void ln_kernel(const float* __restrict__ in,
                          const float* __restrict__ g, const float* __restrict__ b,
                          float* __restrict__ out, h16* __restrict__ oh)
{
    __shared__ float r1[128], r2[128];
    const int row = blockIdx.x;
    const int t = threadIdx.x;
    const float* p = in + (size_t)row * CC;
    float v[4], s = 0.f, sq = 0.f;
    #pragma unroll
    for (int i = 0; i < 4; i++) {
        v[i] = p[t + i * 128];
        s += v[i];
        sq += v[i] * v[i];
    }
    r1[t] = s; r2[t] = sq;
    __syncthreads();
    for (int st = 64; st > 0; st >>= 1) {
        if (t < st) { r1[t] += r1[t + st]; r2[t] += r2[t + st]; }
        __syncthreads();
    }
    float mean = r1[0] * (1.0f / CC);
    float var  = r2[0] * (1.0f / CC) - mean * mean;
    float rstd = rsqrtf(var + 1e-5f);
    #pragma unroll
    for (int i = 0; i < 4; i++) {
        int c = t + i * 128;
        float o = (v[i] - mean) * rstd * g[c] + b[c];
        out[(size_t)row * CC + c] = o;
        if (WHALF) oh[(size_t)row * CC + c] = __float2half_rn(o);
    }
}

// ---------------- CSR scatter-mean ----------------
__global__ void zero_kernel(int* __restrict__ cnt)
{
    int i = blockIdx.x * 256 + threadIdx.x;
    if (i < NN) cnt[i] = 0;
}

__global__ void icount_kernel(const int* __restrict__ dst, int* __restrict__ cnt,
                              int* __restrict__ rank)
{
    int e = blockIdx.x * blockDim.x + threadIdx.x;
    if (e < EE) rank[e] = atomicAdd(&cnt[dst[e]], 1);
}

__global__ void scan_kernel(const int* __restrict__ cnt, int* __restrict__ offs)
{
    __shared__ int a[1024], b[1024];
    int t = threadIdx.x;
    int c0 = cnt[t * 4], c1 = cnt[t * 4 + 1], c2 = cnt[t * 4 + 2], c3 = cnt[t * 4 + 3];
    int ts = c0 + c1 + c2 + c3;
    a[t] = ts;
    __syncthreads();
    int* s = a; int* d = b;
    for (int dd = 1; dd < 1024; dd <<= 1) {
        int v = s[t];
        if (t >= dd) v += s[t - dd];
        d[t] = v;
        __syncthreads();
        int* tmp = s; s = d; d = tmp;
    }
    int pre = s[t] - ts;
    offs[t * 4]     = pre;
    offs[t * 4 + 1] = pre + c0;
    offs[t * 4 + 2] = pre + c0 + c1;
    offs[t * 4 + 3] = pre + c0 + c1 + c2;
}

__global__ void fill_kernel(const int* __restrict__ src, const int* __restrict__ dst,
                            const int* __restrict__ offs, const int* __restrict__ rank,
                            int* __restrict__ out)
{
    int e = blockIdx.x * blockDim.x + threadIdx.x;
    if (e >= EE) return;
    out[offs[dst[e]] + rank[e]] = src[e];
}

__global__ void gather_kernel(const h16* __restrict__ lh, const int* __restrict__ ss,
                              const int* __restrict__ offs, const int* __restrict__ cnt,
                              h16* __restrict__ mean16)
{
    int node = blockIdx.x;
    int off = offs[node], c = cnt[node];
    int col = threadIdx.x * 4;
    float a0 = 0.f, a1 = 0.f, a2 = 0.f, a3 = 0.f;
    for (int j = 0; j < c; j++) {
        int s0 = ss[off + j];
        uint2 v = *(const uint2*)&lh[(size_t)s0 * QL + col];
        float2 f0 = __half22float2(*(__half2*)&v.x);
        float2 f1 = __half22float2(*(__half2*)&v.y);
        a0 += f0.x; a1 += f0.y; a2 += f1.x; a3 += f1.y;
    }
    float inv = 1.f / fmaxf((float)c, 1.f);
    uint2 o;
    o.x = packh2(a0 * inv, a1 * inv);
    o.y = packh2(a2 * inv, a3 * inv);
    *(uint2*)&mean16[(size_t)node * CC + col] = o;
}

// ---------------- launch ----------------
extern "C" void kernel_launch(void* const* d_in, const int* in_sizes, int n_in,
                              void* d_out, int out_size)
{
    const float* x          = (const float*)d_in[0];
    const int*   ei         = (const int*)d_in[1];
    const float* local_w    = (const float*)d_in[2];
    const float* local_b    = (const float*)d_in[3];
    const float* in_proj_w  = (const float*)d_in[4];
    const float* in_proj_b  = (const float*)d_in[5];
    const float* attn_out_w = (const float*)d_in[6];
    const float* attn_out_b = (const float*)d_in[7];
    const float* output_w   = (const float*)d_in[8];
    const float* output_b   = (const float*)d_in[9];
    const float* n1g        = (const float*)d_in[10];
    const float* n1b        = (const float*)d_in[11];
    const float* n2g        = (const float*)d_in[12];
    const float* n2b        = (const float*)d_in[13];
    const float* ffn_w1     = (const float*)d_in[14];
    const float* ffn_b1     = (const float*)d_in[15];
    const float* ffn_w2     = (const float*)d_in[16];
    const float* ffn_b2     = (const float*)d_in[17];
    float* out = (float*)d_out;

    float *Tbuf, *h1, *hid, *h2, *biasq, *biasc;
    int *icnt, *offs, *rank, *ssorted;
    h16 *mean16, *x16, *qw16, *qkvl16, *ctx16, *hid16, *f116;
    h16 *aowT16, *ow16, *cw16, *w116, *w216;

    cudaGetSymbolAddress((void**)&mean16, g_mean16);
    cudaGetSymbolAddress((void**)&icnt,  g_icnt);
    cudaGetSymbolAddress((void**)&offs,  g_offs);
    cudaGetSymbolAddress((void**)&rank,  g_rank);
    cudaGetSymbolAddress((void**)&ssorted, g_ssorted);
    cudaGetSymbolAddress((void**)&x16,   g_x16);
    cudaGetSymbolAddress((void**)&qw16,  g_qw16);
    cudaGetSymbolAddress((void**)&biasq, g_biasq);
    cudaGetSymbolAddress((void**)&qkvl16, g_qkvl16);
    cudaGetSymbolAddress((void**)&ctx16, g_ctx16);
    cudaGetSymbolAddress((void**)&Tbuf,  g_T);
    cudaGetSymbolAddress((void**)&h1,    g_h1);
    cudaGetSymbolAddress((void**)&hid,   g_hid);
    cudaGetSymbolAddress((void**)&hid16, g_hid16);
    cudaGetSymbolAddress((void**)&f116,  g_f116);
    cudaGetSymbolAddress((void**)&h2,    g_h2);
    cudaGetSymbolAddress((void**)&aowT16, g_aowT16);
    cudaGetSymbolAddress((void**)&ow16,  g_ow16);
    cudaGetSymbolAddress((void**)&cw16,  g_cw16);
    cudaGetSymbolAddress((void**)&biasc, g_biasc);
    cudaGetSymbolAddress((void**)&w116,  g_w116);
    cudaGetSymbolAddress((void**)&w216,  g_w216);

    static cudaStream_t s1 = nullptr, s2 = nullptr;
    static cudaEvent_t eStart = nullptr, eCSR = nullptr, eQ = nullptr;
    static cudaEvent_t eQW = nullptr, eW = nullptr, eG = nullptr;
    static bool init_done = false;
    if (!init_done) {
        cudaFuncSetAttribute(flash_kernel,
                             cudaFuncAttributeMaxDynamicSharedMemorySize, 3 * FSTAGE);
        cudaStreamCreateWithFlags(&s1, cudaStreamNonBlocking);
        cudaStreamCreateWithFlags(&s2, cudaStreamNonBlocking);
        cudaEventCreateWithFlags(&eStart, cudaEventDisableTiming);
        cudaEventCreateWithFlags(&eCSR,   cudaEventDisableTiming);
        cudaEventCreateWithFlags(&eQ,     cudaEventDisableTiming);
        cudaEventCreateWithFlags(&eQW,    cudaEventDisableTiming);
        cudaEventCreateWithFlags(&eW,     cudaEventDisableTiming);
        cudaEventCreateWithFlags(&eG,     cudaEventDisableTiming);
        init_done = true;
    }

    cudaEventRecord(eStart, 0);

    // ---- s1: qw convert first (critical-ish), then CSR, then weight prep ----
    cudaStreamWaitEvent(s1, eStart, 0);
    cvt_qw<<<2048, 256, 0, s1>>>(in_proj_w, local_w, in_proj_b, local_b, qw16, biasq);
    cudaEventRecord(eQW, s1);
    zero_kernel<<<(NN + 255) / 256, 256, 0, s1>>>(icnt);
    icount_kernel<<<EE / 256, 256, 0, s1>>>(ei + EE, icnt, rank);
    scan_kernel<<<1, 1024, 0, s1>>>(icnt, offs);
    fill_kernel<<<EE / 256, 256, 0, s1>>>(ei, ei + EE, offs, rank, ssorted);
    cudaEventRecord(eCSR, s1);
    cvt_rest<<<2560, 256, 0, s1>>>(output_w, ffn_w1, ffn_w2, ow16, w116, w216);
    taow_kernel<<<dim3(16, 16), dim3(32, 8), 0, s1>>>(attn_out_w, aowT16);
    gemm_h<EPI_NONE, 0, 1><<<dim3(CC / 128, CC / 128), 256, 0, s1>>>(
        ow16, CC, aowT16, CC, nullptr, cw16, CC, CC, nullptr, nullptr);
    biasc_kernel<<<CC, 128, 0, s1>>>(output_w, attn_out_b, output_b, biasc);
    cudaEventRecord(eW, s1);

    // ---- stream0: x convert + combined qkv/local GEMM ----
    cvt_x<<<4096, 256>>>(x, x16);
    cudaStreamWaitEvent(0, eQW, 0);
    gemm_h<EPI_BIAS, 0, 1><<<dim3(QL / 128, NN / 128), 256>>>(
        x16, CC, qw16, CC, nullptr, qkvl16, QL, CC, biasq, nullptr);
    cudaEventRecord(eQ, 0);

    // ---- s2: gather then T = 0.5*mean@ow^T + bias_comb + x ----
    cudaStreamWaitEvent(s2, eQ, 0);
    cudaStreamWaitEvent(s2, eCSR, 0);
    gather_kernel<<<NN, 128, 0, s2>>>(qkvl16 + 1536, ssorted, offs, icnt, mean16);
    cudaStreamWaitEvent(s2, eW, 0);
    gemm_h<EPI_HALF_BIAS_RES, 1, 0><<<dim3(CC / 128, NN / 128), 256, 0, s2>>>(
        mean16, CC, ow16, CC, Tbuf, nullptr, CC, CC, biasc, x);
    cudaEventRecord(eG, s2);

    // ---- stream0: flash ----
    flash_kernel<<<dim3(NN / 128, HH), 256, 3 * FSTAGE>>>(qkvl16, ctx16);

    // join: h1 = 0.5*ctx@W_comb^T + T
    cudaStreamWaitEvent(0, eG, 0);
    gemm_h<EPI_HALF_RES, 1, 0><<<dim3(CC / 128, NN / 128), 256>>>(
        ctx16, CC, cw16, CC, h1, nullptr, CC, CC, nullptr, Tbuf);

    ln_kernel<1><<<NN, 128>>>(h1, n1g, n1b, hid, hid16);

    gemm_h<EPI_BIAS_GELU, 0, 1><<<dim3(2 * CC / 128, NN / 128), 256>>>(
        hid16, CC, w116, CC, nullptr, f116, 2 * CC, CC, ffn_b1, nullptr);

    gemm_h<EPI_BIAS_RES, 1, 0><<<dim3(CC / 128, NN / 128), 256>>>(
        f116, 2 * CC, w216, 2 * CC, h2, nullptr, CC, 2 * CC, ffn_b2, hid);

    ln_kernel<0><<<NN, 128>>>(h2, n2g, n2b, out, nullptr);
}